// round 6
// baseline (speedup 1.0000x reference)
#include <cuda_runtime.h>
#include <cstdint>

#define B_   8
#define S_   4096
#define D_   1024
#define R_   256
#define BS_  (B_*S_)        // 32768
#define NCH  64
#define CHUNK 64
#define LDT  36
#define STAGE_F (128*LDT)
#define NSTG 3
#define LDE  132

// k45 layout
#define LDA45 260
#define A45_F (128*LDA45)
#define B45_STG_F (128*LDT)
#define K45_SMEM ((A45_F + 4*B45_STG_F)*4)   // 206848 bytes

// ---- device scratch ----
__device__ float g_xm[B_*D_];
__device__ float g_rnorm[BS_];
__device__ float g_fnorm[R_*D_];        // RNA tf32
__device__ float g_gate[B_*R_];
__device__ float g_ret[B_*R_];
__device__ float g_sig[(size_t)BS_*R_]; // locally-scanned (fp32)
__device__ float g_carry[B_*NCH*R_];
__device__ float g_outwt[D_*R_];        // RNA tf32 out_w

__device__ __forceinline__ uint32_t f2tf32(float v) {
    uint32_t u;
    asm("cvt.rna.tf32.f32 %0, %1;" : "=r"(u) : "f"(v));
    return u;
}

__device__ __forceinline__ void mma_tf32(float c[4], uint32_t a0, uint32_t a1,
                                         uint32_t a2, uint32_t a3,
                                         uint32_t b0, uint32_t b1) {
    asm volatile(
        "mma.sync.aligned.m16n8k8.row.col.f32.tf32.tf32.f32 "
        "{%0,%1,%2,%3}, {%4,%5,%6,%7}, {%8,%9}, {%0,%1,%2,%3};"
        : "+f"(c[0]), "+f"(c[1]), "+f"(c[2]), "+f"(c[3])
        : "r"(a0), "r"(a1), "r"(a2), "r"(a3), "r"(b0), "r"(b1));
}

__device__ __forceinline__ void cp16(uint32_t smem_dst, const void* gptr) {
    asm volatile("cp.async.cg.shared.global [%0], [%1], 16;\n"
                 :: "r"(smem_dst), "l"(gptr));
}

// ---- K0 ----
__global__ void k0_zero() {
    int i = blockIdx.x * 1024 + threadIdx.x;
    if (i < B_*D_) g_xm[i] = 0.f;
}

// ---- K1: per-row inverse norms + column sums ----
__global__ __launch_bounds__(256) void k1_stats(const float* __restrict__ x) {
    __shared__ float sxm[8][D_];
    int blk  = blockIdx.x;
    int warp = threadIdx.x >> 5, lane = threadIdx.x & 31;
    float cs[32];
#pragma unroll
    for (int k = 0; k < 32; k++) cs[k] = 0.f;
    int row0 = blk * 128 + warp * 16;
    for (int rr = 0; rr < 16; rr++) {
        int row = row0 + rr;
        const float* xr = x + (size_t)row * D_;
        float ss = 0.f;
#pragma unroll
        for (int k = 0; k < 32; k++) {
            float v = xr[lane + 32*k];
            cs[k] += v;
            ss = fmaf(v, v, ss);
        }
#pragma unroll
        for (int o = 16; o > 0; o >>= 1) ss += __shfl_xor_sync(0xffffffffu, ss, o);
        if (lane == 0) g_rnorm[row] = 1.f / fmaxf(sqrtf(ss), 1e-12f);
    }
#pragma unroll
    for (int k = 0; k < 32; k++) sxm[warp][lane + 32*k] = cs[k];
    __syncthreads();
    int b = (blk * 128) / S_;
    for (int d = threadIdx.x; d < D_; d += 256) {
        float s = 0.f;
#pragma unroll
        for (int w = 0; w < 8; w++) s += sxm[w][d];
        atomicAdd(&g_xm[b*D_ + d], s);
    }
}

// ---- K2: f_norm (RNA tf32) + gate + retention ----
__global__ __launch_bounds__(256) void k2_prep(const float* __restrict__ freq,
                                               const float* __restrict__ rbias,
                                               const float* __restrict__ rw,
                                               const float* __restrict__ gw,
                                               const float* __restrict__ gbias) {
    int r = blockIdx.x;
    int t = threadIdx.x, warp = t >> 5, lane = t & 31;
    __shared__ float red[256];

    const float* fr = freq + (size_t)r * D_;
    float fv[4]; float ss = 0.f;
#pragma unroll
    for (int i = 0; i < 4; i++) { fv[i] = fr[t + 256*i]; ss = fmaf(fv[i], fv[i], ss); }
    red[t] = ss; __syncthreads();
    if (t < 128) red[t] += red[t+128]; __syncthreads();
    if (t < 64)  red[t] += red[t+64];  __syncthreads();
    if (t < 32) {
        float v = red[t] + red[t+32];
#pragma unroll
        for (int o = 16; o > 0; o >>= 1) v += __shfl_xor_sync(0xffffffffu, v, o);
        if (t == 0) red[0] = v;
    }
    __syncthreads();
    float inv = 1.f / fmaxf(sqrtf(red[0]), 1e-12f);
#pragma unroll
    for (int i = 0; i < 4; i++)
        g_fnorm[(size_t)r*D_ + t + 256*i] = __uint_as_float(f2tf32(fv[i] * inv));

    int b = warp;
    const float* gwr = gw + (size_t)r * D_;
    const float* rwr = rw + (size_t)r * D_;
    float ag = 0.f, ar = 0.f;
    const float invS = 1.f / (float)S_;
    for (int k = lane; k < D_; k += 32) {
        float xm = g_xm[b*D_ + k] * invS;
        ag = fmaf(xm, gwr[k], ag);
        ar = fmaf(xm, rwr[k], ar);
    }
#pragma unroll
    for (int o = 16; o > 0; o >>= 1) {
        ag += __shfl_xor_sync(0xffffffffu, ag, o);
        ar += __shfl_xor_sync(0xffffffffu, ar, o);
    }
    if (lane == 0) {
        float gl = ag + gbias[r];
        float gs = 1.f / (1.f + expf(-gl));
        g_gate[b*R_ + r] = (gs >= 0.001f) ? gs : 0.f;
        float rl = ar + rbias[r];
        g_ret[b*R_ + r] = 1.f / (1.f + expf(-rl));
    }
}

// ---- K2b: pre-round out_w to tf32 (RNA) ----
__global__ void k2b_roundw(const float* __restrict__ outw) {
    int i = blockIdx.x * 256 + threadIdx.x;
    g_outwt[i] = __uint_as_float(f2tf32(outw[i]));
}

// ============ tf32 mma.sync compute over one 32-k stage ============
template<int LA, int LB>
__device__ __forceinline__ void gemm_stage(const float* __restrict__ Asb, int ako,
                                           const float* __restrict__ Bsb,
                                           int wm, int wn, int grp, int tid4,
                                           float c[4][4][4]) {
#pragma unroll
    for (int kk = 0; kk < 4; kk++) {
        int koA = ako + kk*8, koB = kk*8;
        uint32_t a[4][4], bf[4][2];
#pragma unroll
        for (int mt = 0; mt < 4; mt++) {
            int m0 = wm*64 + mt*16;
            a[mt][0] = __float_as_uint(Asb[(m0+grp)*LA   + koA + tid4]);
            a[mt][1] = __float_as_uint(Asb[(m0+8+grp)*LA + koA + tid4]);
            a[mt][2] = __float_as_uint(Asb[(m0+grp)*LA   + koA + tid4 + 4]);
            a[mt][3] = __float_as_uint(Asb[(m0+8+grp)*LA + koA + tid4 + 4]);
        }
#pragma unroll
        for (int nt = 0; nt < 4; nt++) {
            int n0 = wn*32 + nt*8;
            bf[nt][0] = __float_as_uint(Bsb[(n0+grp)*LB + koB + tid4]);
            bf[nt][1] = __float_as_uint(Bsb[(n0+grp)*LB + koB + tid4 + 4]);
        }
#pragma unroll
        for (int mt = 0; mt < 4; mt++)
#pragma unroll
            for (int nt = 0; nt < 4; nt++)
                mma_tf32(c[mt][nt], a[mt][0], a[mt][1], a[mt][2], a[mt][3],
                         bf[nt][0], bf[nt][1]);
    }
}

// ---- K3: resonance GEMM + scale + fused chunk-local scan -> g_sig, g_carry ----
__global__ __launch_bounds__(256, 2) void k3_resonance(const float* __restrict__ x) {
    extern __shared__ float smem[];
    float* As = smem;
    float* Bs = smem + NSTG*STAGE_F;
    uint32_t as_b = (uint32_t)__cvta_generic_to_shared(As);
    uint32_t bs_b = (uint32_t)__cvta_generic_to_shared(Bs);

    int nbase = blockIdx.x * 128;
    int mbase = blockIdx.y * 128;
    int t = threadIdx.x;
    int warp = t >> 5, lane = t & 31;
    int wm = warp >> 2, wn = warp & 3;
    int grp = lane >> 2, tid4 = lane & 3;
    int lrow = t >> 3, lk = (t & 7) * 4;

    float c[4][4][4];
#pragma unroll
    for (int mt = 0; mt < 4; mt++)
#pragma unroll
        for (int nt = 0; nt < 4; nt++)
#pragma unroll
            for (int i = 0; i < 4; i++) c[mt][nt][i] = 0.f;

    const float* Ag = x + (size_t)mbase * D_;
    const float* Bg = g_fnorm + (size_t)nbase * D_;

    auto prefetch = [&](int st, int k0) {
        uint32_t ao = as_b + (uint32_t)(st*STAGE_F)*4u;
        uint32_t bo = bs_b + (uint32_t)(st*STAGE_F)*4u;
#pragma unroll
        for (int i = 0; i < 4; i++) {
            int row = lrow + i*32;
            cp16(ao + (uint32_t)(row*LDT + lk)*4u, Ag + (size_t)row*D_ + k0 + lk);
            cp16(bo + (uint32_t)(row*LDT + lk)*4u, Bg + (size_t)row*D_ + k0 + lk);
        }
        asm volatile("cp.async.commit_group;\n");
    };

    const int NK = D_ / 32;
    prefetch(0, 0);
    prefetch(1, 32);
    for (int kt = 0; kt < NK; kt++) {
        if (kt == NK-1) asm volatile("cp.async.wait_group 0;\n");
        else            asm volatile("cp.async.wait_group 1;\n");
        __syncthreads();
        if (kt + 2 < NK) prefetch((kt+2)%NSTG, (kt+2)*32);
        gemm_stage<LDT,LDT>(As + (kt%NSTG)*STAGE_F, 0, Bs + (kt%NSTG)*STAGE_F,
                            wm, wn, grp, tid4, c);
    }

    // fused epilogue: scale -> smem -> chunk-local scan -> g_sig + carries
    __syncthreads();
    float* Es = smem;   // 128 x LDE
    int b = mbase / S_;
#pragma unroll
    for (int mt = 0; mt < 4; mt++) {
        int m0l = wm*64 + mt*16 + grp;
        float rn0 = g_rnorm[mbase + m0l], rn1 = g_rnorm[mbase + m0l + 8];
#pragma unroll
        for (int nt = 0; nt < 4; nt++) {
            int nl = wn*32 + nt*8 + tid4*2;
            float gg0 = g_gate[b*R_ + nbase + nl], gg1 = g_gate[b*R_ + nbase + nl + 1];
            Es[m0l*LDE + nl]       = c[mt][nt][0]*rn0*gg0;
            Es[m0l*LDE + nl + 1]   = c[mt][nt][1]*rn0*gg1;
            Es[(m0l+8)*LDE + nl]   = c[mt][nt][2]*rn1*gg0;
            Es[(m0l+8)*LDE + nl+1] = c[mt][nt][3]*rn1*gg1;
        }
    }
    __syncthreads();

    int ch = t >> 7;
    int n  = t & 127;
    float ret = g_ret[b*R_ + nbase + n];
    size_t gb = ((size_t)(mbase + ch*64)) * R_ + nbase + n;
    float st = 0.f;
#pragma unroll 8
    for (int s = 0; s < CHUNK; s++) {
        st = fmaf(st, ret, Es[(ch*64 + s)*LDE + n]);
        g_sig[gb + (size_t)s*R_] = st;
    }
    int chg = (mbase % S_) / CHUNK + ch;
    g_carry[(b*NCH + chg)*R_ + nbase + n] = st;
}

// ---- K45: fused prefix-apply + output GEMM ----
// one CTA per 128-row m-tile; A static in smem (RNA tf32), B 4-stage ring.
__global__ __launch_bounds__(256, 1) void k45_fused(const float* __restrict__ prev,
                                                    float* __restrict__ out,
                                                    float* __restrict__ fs_out,
                                                    int write_fs) {
    extern __shared__ float smem[];
    float* As = smem;                  // 128 x LDA45
    float* Bs = smem + A45_F;          // 4 stages x 128 x LDT
    uint32_t bs_b = (uint32_t)__cvta_generic_to_shared(Bs);

    int mbase = blockIdx.x * 128;
    int b = mbase / S_;
    int ch0 = (mbase % S_) / CHUNK;    // even
    int t = threadIdx.x;
    int warp = t >> 5, lane = t & 31;
    int wm = warp >> 2, wn = warp & 3;
    int grp = lane >> 2, tid4 = lane & 3;

    // ---- phase 1: prefix-apply, build A tile (tf32 RNA) ----
    {
        int r = t;  // 256 threads = 256 resonators
        float ret = g_ret[b*R_ + r];
        float q = ret;
#pragma unroll
        for (int i = 0; i < 6; i++) q = q * q;   // ret^64
        float e = prev[b*R_ + r];
        for (int j = 0; j < ch0; j++)
            e = fmaf(e, q, g_carry[(b*NCH + j)*R_ + r]);
        float e1 = fmaf(e, q, g_carry[(b*NCH + ch0)*R_ + r]);

        const float* sg = g_sig + (size_t)mbase * R_ + r;
        float er = e;
        float last = 0.f;
#pragma unroll 4
        for (int s = 0; s < 64; s++) {
            er *= ret;
            float v = sg[(size_t)s * R_] + er;
            As[s*LDA45 + r] = __uint_as_float(f2tf32(v));
        }
        er = e1;
#pragma unroll 4
        for (int s = 64; s < 128; s++) {
            er *= ret;
            float v = sg[(size_t)s * R_] + er;
            As[s*LDA45 + r] = __uint_as_float(f2tf32(v));
            last = v;
        }
        if (write_fs && (mbase % S_) == S_ - 128)
            fs_out[b*R_ + r] = last;
    }
    __syncthreads();

    // ---- phase 2: GEMM 128x1024 = A(128x256) @ outwt^T, 8 n-tiles ----
    int lrow = t >> 3, lk = (t & 7) * 4;
    auto fillB = [&](int it2) {
        int st = it2 & 3;
        int ntile = it2 >> 3, kt = it2 & 7;
        const float* Bg = g_outwt + (size_t)(ntile*128) * R_ + kt*32;
        uint32_t bo = bs_b + (uint32_t)(st*B45_STG_F)*4u;
#pragma unroll
        for (int i = 0; i < 4; i++) {
            int row = lrow + i*32;
            cp16(bo + (uint32_t)(row*LDT + lk)*4u, Bg + (size_t)row*R_ + lk);
        }
        asm volatile("cp.async.commit_group;\n");
    };

    float c[4][4][4];
#pragma unroll
    for (int mt = 0; mt < 4; mt++)
#pragma unroll
        for (int nt = 0; nt < 4; nt++)
#pragma unroll
            for (int i = 0; i < 4; i++) c[mt][nt][i] = 0.f;

    fillB(0); fillB(1); fillB(2);
    for (int it = 0; it < 64; it++) {
        asm volatile("cp.async.wait_group 2;\n");
        __syncthreads();
        if (it + 3 < 64) fillB(it + 3);
        int kt = it & 7;
        gemm_stage<LDA45,LDT>(As, kt*32, Bs + (it & 3)*B45_STG_F,
                              wm, wn, grp, tid4, c);
        if (kt == 7) {
            int nbase = (it >> 3) * 128;
#pragma unroll
            for (int mt = 0; mt < 4; mt++) {
                int m0 = mbase + wm*64 + mt*16 + grp;
#pragma unroll
                for (int nt = 0; nt < 4; nt++) {
                    int n = nbase + wn*32 + nt*8 + tid4*2;
                    float2 v0 = make_float2(c[mt][nt][0], c[mt][nt][1]);
                    float2 v1 = make_float2(c[mt][nt][2], c[mt][nt][3]);
                    *(float2*)&out[(size_t)m0*D_ + n]     = v0;
                    *(float2*)&out[(size_t)(m0+8)*D_ + n] = v1;
                    c[mt][nt][0] = c[mt][nt][1] = c[mt][nt][2] = c[mt][nt][3] = 0.f;
                }
            }
        }
    }
}

extern "C" void kernel_launch(void* const* d_in, const int* in_sizes, int n_in,
                              void* d_out, int out_size) {
    const float* x     = (const float*)d_in[0];
    const float* prev  = (const float*)d_in[1];
    const float* freq  = (const float*)d_in[2];
    const float* rbias = (const float*)d_in[3];
    const float* rw    = (const float*)d_in[4];
    const float* gw    = (const float*)d_in[5];
    const float* gbias = (const float*)d_in[6];
    const float* outw  = (const float*)d_in[7];
    float* out = (float*)d_out;

    const int SMEM_K3 = NSTG * 2 * STAGE_F * 4;   // 110592
    cudaFuncSetAttribute(k3_resonance, cudaFuncAttributeMaxDynamicSharedMemorySize, SMEM_K3);
    cudaFuncSetAttribute(k45_fused,    cudaFuncAttributeMaxDynamicSharedMemorySize, K45_SMEM);

    const int out_elems = B_*S_*D_;
    int write_fs = (out_size >= out_elems + B_*R_) ? 1 : 0;
    float* fs = out + out_elems;

    k0_zero<<<8, 1024>>>();
    k1_stats<<<256, 256>>>(x);
    k2_prep<<<256, 256>>>(freq, rbias, rw, gw, gbias);
    k2b_roundw<<<(D_*R_)/256, 256>>>(outw);
    k3_resonance<<<dim3(2, 256), 256, SMEM_K3>>>(x);
    k45_fused<<<BS_/128, 256, K45_SMEM>>>(prev, out, fs, write_fs);
}

// round 7
// speedup vs baseline: 1.8487x; 1.8487x over previous
#include <cuda_runtime.h>
#include <cuda_fp16.h>
#include <cstdint>

#define B_   8
#define S_   4096
#define D_   1024
#define R_   256
#define BS_  (B_*S_)        // 32768
#define NCH  64
#define CHUNK 64
#define LH   40              // smem stage pitch in halves (80B rows)
#define STAGE_H (128*LH)     // halves per stage per operand
#define STAGE_B (STAGE_H*2)  // 10240 bytes
#define LDE  132

// ---- device scratch ----
__device__ float  g_xm[B_*D_];
__device__ __half g_xhn[(size_t)BS_*D_];   // fp16(x * rnorm)
__device__ __half g_fnh[R_*D_];            // fp16 normalized freqs
__device__ float  g_gate[B_*R_];
__device__ float  g_ret[B_*R_];
__device__ float  g_sig[(size_t)BS_*R_];   // locally-scanned (fp32)
__device__ __half g_sigh[(size_t)BS_*R_];  // fully-scanned (fp16)
__device__ float  g_carry[B_*NCH*R_];
__device__ __half g_outwh[D_*R_];          // fp16 out_w

__device__ __forceinline__ void mma_f16(float c[4], uint32_t a0, uint32_t a1,
                                        uint32_t a2, uint32_t a3,
                                        uint32_t b0, uint32_t b1) {
    asm volatile(
        "mma.sync.aligned.m16n8k16.row.col.f32.f16.f16.f32 "
        "{%0,%1,%2,%3}, {%4,%5,%6,%7}, {%8,%9}, {%0,%1,%2,%3};"
        : "+f"(c[0]), "+f"(c[1]), "+f"(c[2]), "+f"(c[3])
        : "r"(a0), "r"(a1), "r"(a2), "r"(a3), "r"(b0), "r"(b1));
}

__device__ __forceinline__ void ldsm4(uint32_t r[4], uint32_t addr) {
    asm volatile("ldmatrix.sync.aligned.m8n8.x4.shared.b16 {%0,%1,%2,%3}, [%4];"
                 : "=r"(r[0]), "=r"(r[1]), "=r"(r[2]), "=r"(r[3]) : "r"(addr));
}

__device__ __forceinline__ void cp16(uint32_t smem_dst, const void* gptr) {
    asm volatile("cp.async.cg.shared.global [%0], [%1], 16;\n"
                 :: "r"(smem_dst), "l"(gptr));
}

// ---- K0 ----
__global__ void k0_zero() {
    int i = blockIdx.x * 1024 + threadIdx.x;
    if (i < B_*D_) g_xm[i] = 0.f;
}

// ---- K1: row norms -> write x_hn = fp16(x*rnorm); column sums for mean ----
__global__ __launch_bounds__(256) void k1_stats(const float* __restrict__ x) {
    __shared__ float sxm[8][D_];   // 32KB
    int blk  = blockIdx.x;         // 256 blocks x 128 rows
    int warp = threadIdx.x >> 5, lane = threadIdx.x & 31;
    float cs[32];
#pragma unroll
    for (int k = 0; k < 32; k++) cs[k] = 0.f;
    int row0 = blk * 128 + warp * 16;
    for (int rr = 0; rr < 16; rr++) {
        int row = row0 + rr;
        const float2* xr2 = (const float2*)(x + (size_t)row * D_);
        float vx[16], vy[16];
        float ss = 0.f;
#pragma unroll
        for (int k = 0; k < 16; k++) {
            float2 v = xr2[lane + 32*k];
            vx[k] = v.x; vy[k] = v.y;
            cs[2*k]   += v.x;
            cs[2*k+1] += v.y;
            ss = fmaf(v.x, v.x, fmaf(v.y, v.y, ss));
        }
#pragma unroll
        for (int o = 16; o > 0; o >>= 1) ss += __shfl_xor_sync(0xffffffffu, ss, o);
        float rn = 1.f / fmaxf(sqrtf(ss), 1e-12f);
        __half2* dst = (__half2*)g_xhn + (size_t)row * (D_/2);
#pragma unroll
        for (int k = 0; k < 16; k++)
            dst[lane + 32*k] = __floats2half2_rn(vx[k]*rn, vy[k]*rn);
    }
#pragma unroll
    for (int k = 0; k < 16; k++) {
        sxm[warp][2*(lane + 32*k)]     = cs[2*k];
        sxm[warp][2*(lane + 32*k) + 1] = cs[2*k+1];
    }
    __syncthreads();
    int b = (blk * 128) / S_;
    for (int d = threadIdx.x; d < D_; d += 256) {
        float s = 0.f;
#pragma unroll
        for (int w = 0; w < 8; w++) s += sxm[w][d];
        atomicAdd(&g_xm[b*D_ + d], s);
    }
}

// ---- K2: f_norm (fp16) + gate + retention ----
__global__ __launch_bounds__(256) void k2_prep(const float* __restrict__ freq,
                                               const float* __restrict__ rbias,
                                               const float* __restrict__ rw,
                                               const float* __restrict__ gw,
                                               const float* __restrict__ gbias) {
    int r = blockIdx.x;
    int t = threadIdx.x, warp = t >> 5, lane = t & 31;
    __shared__ float red[256];

    const float2* fr2 = (const float2*)(freq + (size_t)r * D_);
    float2 fv[2]; float ss = 0.f;
#pragma unroll
    for (int i = 0; i < 2; i++) {
        fv[i] = fr2[t + 256*i];
        ss = fmaf(fv[i].x, fv[i].x, fmaf(fv[i].y, fv[i].y, ss));
    }
    red[t] = ss; __syncthreads();
    if (t < 128) red[t] += red[t+128]; __syncthreads();
    if (t < 64)  red[t] += red[t+64];  __syncthreads();
    if (t < 32) {
        float v = red[t] + red[t+32];
#pragma unroll
        for (int o = 16; o > 0; o >>= 1) v += __shfl_xor_sync(0xffffffffu, v, o);
        if (t == 0) red[0] = v;
    }
    __syncthreads();
    float inv = 1.f / fmaxf(sqrtf(red[0]), 1e-12f);
    __half2* dst = (__half2*)g_fnh + (size_t)r * (D_/2);
#pragma unroll
    for (int i = 0; i < 2; i++)
        dst[t + 256*i] = __floats2half2_rn(fv[i].x*inv, fv[i].y*inv);

    int b = warp;
    const float* gwr = gw + (size_t)r * D_;
    const float* rwr = rw + (size_t)r * D_;
    float ag = 0.f, ar = 0.f;
    const float invS = 1.f / (float)S_;
    for (int k = lane; k < D_; k += 32) {
        float xm = g_xm[b*D_ + k] * invS;
        ag = fmaf(xm, gwr[k], ag);
        ar = fmaf(xm, rwr[k], ar);
    }
#pragma unroll
    for (int o = 16; o > 0; o >>= 1) {
        ag += __shfl_xor_sync(0xffffffffu, ag, o);
        ar += __shfl_xor_sync(0xffffffffu, ar, o);
    }
    if (lane == 0) {
        float gl = ag + gbias[r];
        float gs = 1.f / (1.f + expf(-gl));
        g_gate[b*R_ + r] = (gs >= 0.001f) ? gs : 0.f;
        float rl = ar + rbias[r];
        g_ret[b*R_ + r] = 1.f / (1.f + expf(-rl));
    }
}

// ---- K2b: out_w -> fp16 ----
__global__ void k2b_roundw(const float* __restrict__ outw) {
    int i = blockIdx.x * 256 + threadIdx.x;   // half2 index
    float2 v = ((const float2*)outw)[i];
    ((__half2*)g_outwh)[i] = __floats2half2_rn(v.x, v.y);
}

// ============ fp16 mma compute over one 32-k stage ============
// A via ldmatrix x4 (pitch LH), B via scalar LDS.b32 (pitch LH)
__device__ __forceinline__ void gemm16_stage(uint32_t as_byte, const __half* __restrict__ Bsb,
                                             int wm, int wn, int grp, int tid4, int lane,
                                             float c[4][4][4]) {
#pragma unroll
    for (int kk = 0; kk < 2; kk++) {
        int ko = kk * 16;
        uint32_t a[4][4], bf[4][2];
        uint32_t lofs = (uint32_t)(((lane & 15) * LH + ((lane >> 4) << 3)) * 2);
#pragma unroll
        for (int mt = 0; mt < 4; mt++) {
            uint32_t addr = as_byte + (uint32_t)(((wm*64 + mt*16) * LH + ko) * 2) + lofs;
            ldsm4(a[mt], addr);
        }
#pragma unroll
        for (int nt = 0; nt < 4; nt++) {
            const __half* bp = Bsb + (wn*32 + nt*8 + grp) * LH + ko + tid4*2;
            bf[nt][0] = *(const uint32_t*)bp;
            bf[nt][1] = *(const uint32_t*)(bp + 8);
        }
#pragma unroll
        for (int mt = 0; mt < 4; mt++)
#pragma unroll
            for (int nt = 0; nt < 4; nt++)
                mma_f16(c[mt][nt], a[mt][0], a[mt][1], a[mt][2], a[mt][3],
                        bf[nt][0], bf[nt][1]);
    }
}

// ---- K3: resonance GEMM (fp16) + gate scale + fused chunk-local scan ----
__global__ __launch_bounds__(256, 2) void k3_resonance() {
    extern __shared__ float smem[];
    __half* hs = (__half*)smem;
    uint32_t sb = (uint32_t)__cvta_generic_to_shared(smem);

    int nbase = blockIdx.x * 128;
    int mbase = blockIdx.y * 128;
    int t = threadIdx.x;
    int warp = t >> 5, lane = t & 31;
    int wm = warp >> 2, wn = warp & 3;
    int grp = lane >> 2, tid4 = lane & 3;

    float c[4][4][4];
#pragma unroll
    for (int mt = 0; mt < 4; mt++)
#pragma unroll
        for (int nt = 0; nt < 4; nt++)
#pragma unroll
            for (int i = 0; i < 4; i++) c[mt][nt][i] = 0.f;

    const __half* Ag = g_xhn + (size_t)mbase * D_;
    const __half* Bg = g_fnh + (size_t)nbase * D_;

    auto prefetch = [&](int st, int kt) {
        uint32_t ao = sb + (uint32_t)(st * STAGE_B);
        uint32_t bo = sb + (uint32_t)((3 + st) * STAGE_B);
        int k0 = kt * 32;
#pragma unroll
        for (int i = 0; i < 2; i++) {
            int id = t + i*256;
            int row = id >> 2, seg = id & 3;
            cp16(ao + (uint32_t)((row*LH + seg*8) * 2), Ag + (size_t)row*D_ + k0 + seg*8);
            cp16(bo + (uint32_t)((row*LH + seg*8) * 2), Bg + (size_t)row*D_ + k0 + seg*8);
        }
        asm volatile("cp.async.commit_group;\n");
    };

    const int NK = D_ / 32;   // 32
    prefetch(0, 0);
    prefetch(1, 1);
    for (int kt = 0; kt < NK; kt++) {
        if (kt == NK-1) asm volatile("cp.async.wait_group 0;\n");
        else            asm volatile("cp.async.wait_group 1;\n");
        __syncthreads();
        if (kt + 2 < NK) prefetch((kt+2) % 3, kt+2);
        int st = kt % 3;
        gemm16_stage(sb + (uint32_t)(st*STAGE_B), hs + (3 + st)*STAGE_H,
                     wm, wn, grp, tid4, lane, c);
    }

    // fused epilogue: gate scale -> Es -> chunk-local scan -> g_sig + carries
    __syncthreads();
    float* Es = smem;   // 128 x LDE floats
    int b = mbase / S_;
#pragma unroll
    for (int mt = 0; mt < 4; mt++) {
        int m0l = wm*64 + mt*16 + grp;
#pragma unroll
        for (int nt = 0; nt < 4; nt++) {
            int nl = wn*32 + nt*8 + tid4*2;
            float gg0 = g_gate[b*R_ + nbase + nl], gg1 = g_gate[b*R_ + nbase + nl + 1];
            Es[m0l*LDE + nl]       = c[mt][nt][0]*gg0;
            Es[m0l*LDE + nl + 1]   = c[mt][nt][1]*gg1;
            Es[(m0l+8)*LDE + nl]   = c[mt][nt][2]*gg0;
            Es[(m0l+8)*LDE + nl+1] = c[mt][nt][3]*gg1;
        }
    }
    __syncthreads();

    int ch = t >> 7;
    int n  = t & 127;
    float ret = g_ret[b*R_ + nbase + n];
    size_t gb = ((size_t)(mbase + ch*64)) * R_ + nbase + n;
    float st = 0.f;
#pragma unroll 8
    for (int s = 0; s < CHUNK; s++) {
        st = fmaf(st, ret, Es[(ch*64 + s)*LDE + n]);
        g_sig[gb + (size_t)s*R_] = st;
    }
    int chg = (mbase % S_) / CHUNK + ch;
    g_carry[(b*NCH + chg)*R_ + nbase + n] = st;
}

// ---- K4: apply chunk prefixes; write fp16 scanned signal; final_state fp32 ----
__global__ __launch_bounds__(256) void k_scan2(const float* __restrict__ prev,
                                               float* __restrict__ fs_out,
                                               int write_fs) {
    int blk = blockIdx.x;
    int b = blk / NCH, ch = blk % NCH;
    int r = threadIdx.x;
    float ret = g_ret[b*R_ + r];
    float q = ret;
#pragma unroll
    for (int i = 0; i < 6; i++) q = q * q;   // ret^64
    float e = prev[b*R_ + r];
    for (int j = 0; j < ch; j++)
        e = fmaf(e, q, g_carry[(b*NCH + j)*R_ + r]);

    size_t base = ((size_t)(b*S_ + ch*CHUNK)) * R_ + r;
    float p = ret;
    float last = 0.f;
    for (int g = 0; g < CHUNK/8; g++) {
        float v[8];
#pragma unroll
        for (int j = 0; j < 8; j++) v[j] = g_sig[base + (size_t)(g*8+j)*R_];
#pragma unroll
        for (int j = 0; j < 8; j++) {
            float o = fmaf(e, p, v[j]);
            g_sigh[base + (size_t)(g*8+j)*R_] = __float2half_rn(o);
            p *= ret;
            last = o;
        }
    }
    if (write_fs && ch == NCH-1)
        fs_out[b*R_ + r] = last;
}

// ---- K5: output GEMM (fp16): acc @ out_w^T ----
__global__ __launch_bounds__(256, 2) void k5_output(float* __restrict__ out) {
    extern __shared__ float smem[];
    __half* hs = (__half*)smem;
    uint32_t sb = (uint32_t)__cvta_generic_to_shared(smem);

    int nbase = blockIdx.x * 128;
    int mbase = blockIdx.y * 128;
    int t = threadIdx.x;
    int warp = t >> 5, lane = t & 31;
    int wm = warp >> 2, wn = warp & 3;
    int grp = lane >> 2, tid4 = lane & 3;

    float c[4][4][4];
#pragma unroll
    for (int mt = 0; mt < 4; mt++)
#pragma unroll
        for (int nt = 0; nt < 4; nt++)
#pragma unroll
            for (int i = 0; i < 4; i++) c[mt][nt][i] = 0.f;

    const __half* Ag = g_sigh + (size_t)mbase * R_;
    const __half* Bg = g_outwh + (size_t)nbase * R_;

    auto prefetch = [&](int st, int kt) {
        uint32_t ao = sb + (uint32_t)(st * STAGE_B);
        uint32_t bo = sb + (uint32_t)((3 + st) * STAGE_B);
        int k0 = kt * 32;
#pragma unroll
        for (int i = 0; i < 2; i++) {
            int id = t + i*256;
            int row = id >> 2, seg = id & 3;
            cp16(ao + (uint32_t)((row*LH + seg*8) * 2), Ag + (size_t)row*R_ + k0 + seg*8);
            cp16(bo + (uint32_t)((row*LH + seg*8) * 2), Bg + (size_t)row*R_ + k0 + seg*8);
        }
        asm volatile("cp.async.commit_group;\n");
    };

    const int NK = R_ / 32;   // 8
    prefetch(0, 0);
    prefetch(1, 1);
    for (int kt = 0; kt < NK; kt++) {
        if (kt == NK-1) asm volatile("cp.async.wait_group 0;\n");
        else            asm volatile("cp.async.wait_group 1;\n");
        __syncthreads();
        if (kt + 2 < NK) prefetch((kt+2) % 3, kt+2);
        int st = kt % 3;
        gemm16_stage(sb + (uint32_t)(st*STAGE_B), hs + (3 + st)*STAGE_H,
                     wm, wn, grp, tid4, lane, c);
    }

#pragma unroll
    for (int mt = 0; mt < 4; mt++) {
        int m0 = mbase + wm*64 + mt*16 + grp;
#pragma unroll
        for (int nt = 0; nt < 4; nt++) {
            int n = nbase + wn*32 + nt*8 + tid4*2;
            float2 v0 = make_float2(c[mt][nt][0], c[mt][nt][1]);
            float2 v1 = make_float2(c[mt][nt][2], c[mt][nt][3]);
            *(float2*)&out[(size_t)m0*D_ + n]     = v0;
            *(float2*)&out[(size_t)(m0+8)*D_ + n] = v1;
        }
    }
}

extern "C" void kernel_launch(void* const* d_in, const int* in_sizes, int n_in,
                              void* d_out, int out_size) {
    const float* x     = (const float*)d_in[0];
    const float* prev  = (const float*)d_in[1];
    const float* freq  = (const float*)d_in[2];
    const float* rbias = (const float*)d_in[3];
    const float* rw    = (const float*)d_in[4];
    const float* gw    = (const float*)d_in[5];
    const float* gbias = (const float*)d_in[6];
    const float* outw  = (const float*)d_in[7];
    float* out = (float*)d_out;

    const int SMEM_K3 = 128*LDE*4;        // 67584 (> 6*STAGE_B = 61440)
    const int SMEM_K5 = 6*STAGE_B;        // 61440
    cudaFuncSetAttribute(k3_resonance, cudaFuncAttributeMaxDynamicSharedMemorySize, SMEM_K3);
    cudaFuncSetAttribute(k5_output,    cudaFuncAttributeMaxDynamicSharedMemorySize, SMEM_K5);

    const int out_elems = B_*S_*D_;
    int write_fs = (out_size >= out_elems + B_*R_) ? 1 : 0;
    float* fs = out + out_elems;

    k0_zero<<<8, 1024>>>();
    k1_stats<<<256, 256>>>(x);
    k2_prep<<<256, 256>>>(freq, rbias, rw, gw, gbias);
    k2b_roundw<<<(D_*R_)/512, 256>>>(outw);
    k3_resonance<<<dim3(2, 256), 256, SMEM_K3>>>();
    k_scan2<<<B_*NCH, 256>>>(prev, fs, write_fs);
    k5_output<<<dim3(8, 256), 256, SMEM_K5>>>(out);
}

// round 10
// speedup vs baseline: 2.0220x; 1.0937x over previous
#include <cuda_runtime.h>
#include <cuda_fp16.h>
#include <cstdint>

#define B_   8
#define S_   4096
#define D_   1024
#define R_   256
#define BS_  (B_*S_)        // 32768
#define NCH  64
#define CHUNK 64
#define LH   40              // smem pitch in halves (80B rows)
#define STAGE_H (128*LH)
#define STAGE_B (STAGE_H*2)  // 10240 bytes
#define NST  4
#define LDE  132

// ---- device scratch ----
__device__ float  g_xm[B_*D_];
__device__ __half g_xhn[(size_t)BS_*D_];   // fp16(x * rnorm)
__device__ __half g_fnh[R_*D_];            // fp16 normalized freqs
__device__ float  g_gate[B_*R_];
__device__ float  g_ret[B_*R_];
__device__ __half g_sigh[(size_t)BS_*R_];  // local-scan (fp16) -> full-scan (fp16)
__device__ float  g_carry[B_*NCH*R_];
__device__ __half g_outwh[D_*R_];          // fp16 out_w

__device__ __forceinline__ void mma_f16(float c[4], uint32_t a0, uint32_t a1,
                                        uint32_t a2, uint32_t a3,
                                        uint32_t b0, uint32_t b1) {
    asm volatile(
        "mma.sync.aligned.m16n8k16.row.col.f32.f16.f16.f32 "
        "{%0,%1,%2,%3}, {%4,%5,%6,%7}, {%8,%9}, {%0,%1,%2,%3};"
        : "+f"(c[0]), "+f"(c[1]), "+f"(c[2]), "+f"(c[3])
        : "r"(a0), "r"(a1), "r"(a2), "r"(a3), "r"(b0), "r"(b1));
}

__device__ __forceinline__ void ldsm4(uint32_t r[4], uint32_t addr) {
    asm volatile("ldmatrix.sync.aligned.m8n8.x4.shared.b16 {%0,%1,%2,%3}, [%4];"
                 : "=r"(r[0]), "=r"(r[1]), "=r"(r[2]), "=r"(r[3]) : "r"(addr));
}

__device__ __forceinline__ void cp16(uint32_t smem_dst, const void* gptr) {
    asm volatile("cp.async.cg.shared.global [%0], [%1], 16;\n"
                 :: "r"(smem_dst), "l"(gptr));
}

// ---- K0 ----
__global__ void k0_zero() {
    int i = blockIdx.x * 1024 + threadIdx.x;
    if (i < B_*D_) g_xm[i] = 0.f;
}

// ---- K1: row norms -> x_hn = fp16(x*rnorm); column sums ----
__global__ __launch_bounds__(256) void k1_stats(const float* __restrict__ x) {
    __shared__ float sxm[8][D_];
    int blk  = blockIdx.x;
    int warp = threadIdx.x >> 5, lane = threadIdx.x & 31;
    float cs[32];
#pragma unroll
    for (int k = 0; k < 32; k++) cs[k] = 0.f;
    int row0 = blk * 128 + warp * 16;
    for (int rr = 0; rr < 16; rr++) {
        int row = row0 + rr;
        const float2* xr2 = (const float2*)(x + (size_t)row * D_);
        float vx[16], vy[16];
        float ss = 0.f;
#pragma unroll
        for (int k = 0; k < 16; k++) {
            float2 v = xr2[lane + 32*k];
            vx[k] = v.x; vy[k] = v.y;
            cs[2*k]   += v.x;
            cs[2*k+1] += v.y;
            ss = fmaf(v.x, v.x, fmaf(v.y, v.y, ss));
        }
#pragma unroll
        for (int o = 16; o > 0; o >>= 1) ss += __shfl_xor_sync(0xffffffffu, ss, o);
        float rn = 1.f / fmaxf(sqrtf(ss), 1e-12f);
        __half2* dst = (__half2*)g_xhn + (size_t)row * (D_/2);
#pragma unroll
        for (int k = 0; k < 16; k++)
            dst[lane + 32*k] = __floats2half2_rn(vx[k]*rn, vy[k]*rn);
    }
#pragma unroll
    for (int k = 0; k < 16; k++) {
        sxm[warp][2*(lane + 32*k)]     = cs[2*k];
        sxm[warp][2*(lane + 32*k) + 1] = cs[2*k+1];
    }
    __syncthreads();
    int b = (blk * 128) / S_;
    for (int d = threadIdx.x; d < D_; d += 256) {
        float s = 0.f;
#pragma unroll
        for (int w = 0; w < 8; w++) s += sxm[w][d];
        atomicAdd(&g_xm[b*D_ + d], s);
    }
}

// ---- K2: f_norm (fp16) + gate + retention ----
__global__ __launch_bounds__(256) void k2_prep(const float* __restrict__ freq,
                                               const float* __restrict__ rbias,
                                               const float* __restrict__ rw,
                                               const float* __restrict__ gw,
                                               const float* __restrict__ gbias) {
    int r = blockIdx.x;
    int t = threadIdx.x, warp = t >> 5, lane = t & 31;
    __shared__ float red[256];

    const float2* fr2 = (const float2*)(freq + (size_t)r * D_);
    float2 fv[2]; float ss = 0.f;
#pragma unroll
    for (int i = 0; i < 2; i++) {
        fv[i] = fr2[t + 256*i];
        ss = fmaf(fv[i].x, fv[i].x, fmaf(fv[i].y, fv[i].y, ss));
    }
    red[t] = ss; __syncthreads();
    if (t < 128) red[t] += red[t+128]; __syncthreads();
    if (t < 64)  red[t] += red[t+64];  __syncthreads();
    if (t < 32) {
        float v = red[t] + red[t+32];
#pragma unroll
        for (int o = 16; o > 0; o >>= 1) v += __shfl_xor_sync(0xffffffffu, v, o);
        if (t == 0) red[0] = v;
    }
    __syncthreads();
    float inv = 1.f / fmaxf(sqrtf(red[0]), 1e-12f);
    __half2* dst = (__half2*)g_fnh + (size_t)r * (D_/2);
#pragma unroll
    for (int i = 0; i < 2; i++)
        dst[t + 256*i] = __floats2half2_rn(fv[i].x*inv, fv[i].y*inv);

    int b = warp;
    const float* gwr = gw + (size_t)r * D_;
    const float* rwr = rw + (size_t)r * D_;
    float ag = 0.f, ar = 0.f;
    const float invS = 1.f / (float)S_;
    for (int k = lane; k < D_; k += 32) {
        float xm = g_xm[b*D_ + k] * invS;
        ag = fmaf(xm, gwr[k], ag);
        ar = fmaf(xm, rwr[k], ar);
    }
#pragma unroll
    for (int o = 16; o > 0; o >>= 1) {
        ag += __shfl_xor_sync(0xffffffffu, ag, o);
        ar += __shfl_xor_sync(0xffffffffu, ar, o);
    }
    if (lane == 0) {
        float gl = ag + gbias[r];
        float gs = 1.f / (1.f + expf(-gl));
        g_gate[b*R_ + r] = (gs >= 0.001f) ? gs : 0.f;
        float rl = ar + rbias[r];
        g_ret[b*R_ + r] = 1.f / (1.f + expf(-rl));
    }
}

// ---- K2b: out_w -> fp16 ----
__global__ void k2b_roundw(const float* __restrict__ outw) {
    int i = blockIdx.x * 256 + threadIdx.x;
    float2 v = ((const float2*)outw)[i];
    ((__half2*)g_outwh)[i] = __floats2half2_rn(v.x, v.y);
}

// ============ fp16 mma over one 32-k stage: A ldsm.x4, B ldsm.x4 ============
__device__ __forceinline__ void gemm16_stage(uint32_t as_byte, uint32_t bs_byte,
                                             int wm, int wn, int lane,
                                             float c[4][4][4]) {
    uint32_t a_lofs = (uint32_t)(((lane & 15) * LH + ((lane >> 4) << 3)) * 2);
    int bj = lane >> 3, brr = lane & 7;           // matrix idx, row-in-matrix
    int b_nofs = ((bj >> 1) << 3) + brr;          // +8 for matrices 2,3
    int b_kofs = (bj & 1) << 3;                   // +8 halves for odd matrices
#pragma unroll
    for (int kk = 0; kk < 2; kk++) {
        int ko = kk * 16;
        uint32_t a[4][4], bf[4][4];
#pragma unroll
        for (int mt = 0; mt < 4; mt++) {
            uint32_t addr = as_byte + (uint32_t)(((wm*64 + mt*16) * LH + ko) * 2) + a_lofs;
            ldsm4(a[mt], addr);
        }
#pragma unroll
        for (int p = 0; p < 2; p++) {
            int nrow = wn*32 + p*16 + b_nofs;
            uint32_t addr = bs_byte + (uint32_t)((nrow*LH + ko + b_kofs) * 2);
            ldsm4(bf[p], addr);   // bf[p] = {nt=2p k0-7, nt=2p k8-15, nt=2p+1 k0-7, nt=2p+1 k8-15}
        }
#pragma unroll
        for (int mt = 0; mt < 4; mt++)
#pragma unroll
            for (int nt = 0; nt < 4; nt++)
                mma_f16(c[mt][nt], a[mt][0], a[mt][1], a[mt][2], a[mt][3],
                        bf[nt>>1][(nt&1)*2], bf[nt>>1][(nt&1)*2 + 1]);
    }
}

// ---- K3: resonance GEMM (fp16) + gate scale + fused chunk-local scan ----
__global__ __launch_bounds__(256, 2) void k3_resonance() {
    extern __shared__ float smem[];
    uint32_t sb = (uint32_t)__cvta_generic_to_shared(smem);

    int nbase = blockIdx.x * 128;
    int mbase = blockIdx.y * 128;
    int t = threadIdx.x;
    int warp = t >> 5, lane = t & 31;
    int wm = warp >> 2, wn = warp & 3;
    int grp = lane >> 2, tid4 = lane & 3;

    float c[4][4][4];
#pragma unroll
    for (int mt = 0; mt < 4; mt++)
#pragma unroll
        for (int nt = 0; nt < 4; nt++)
#pragma unroll
            for (int i = 0; i < 4; i++) c[mt][nt][i] = 0.f;

    const __half* Ag = g_xhn + (size_t)mbase * D_;
    const __half* Bg = g_fnh + (size_t)nbase * D_;

    auto prefetch = [&](int st, int kt) {
        uint32_t ao = sb + (uint32_t)(st * STAGE_B);
        uint32_t bo = sb + (uint32_t)((NST + st) * STAGE_B);
        int k0 = kt * 32;
#pragma unroll
        for (int i = 0; i < 2; i++) {
            int id = t + i*256;
            int row = id >> 2, seg = id & 3;
            cp16(ao + (uint32_t)((row*LH + seg*8) * 2), Ag + (size_t)row*D_ + k0 + seg*8);
            cp16(bo + (uint32_t)((row*LH + seg*8) * 2), Bg + (size_t)row*D_ + k0 + seg*8);
        }
        asm volatile("cp.async.commit_group;\n");
    };

    const int NK = D_ / 32;   // 32
    prefetch(0, 0); prefetch(1, 1); prefetch(2, 2);
    for (int kt = 0; kt < NK; kt++) {
        if (kt <= NK-3)      asm volatile("cp.async.wait_group 2;\n");
        else if (kt == NK-2) asm volatile("cp.async.wait_group 1;\n");
        else                 asm volatile("cp.async.wait_group 0;\n");
        __syncthreads();
        if (kt + 3 < NK) prefetch((kt+3) % NST, kt+3);
        int st = kt % NST;
        gemm16_stage(sb + (uint32_t)(st*STAGE_B), sb + (uint32_t)((NST+st)*STAGE_B),
                     wm, wn, lane, c);
    }

    // fused epilogue: gate scale -> Es -> chunk-local scan -> g_sigh + carries
    __syncthreads();
    float* Es = smem;   // 128 x LDE floats
    int b = mbase / S_;
#pragma unroll
    for (int mt = 0; mt < 4; mt++) {
        int m0l = wm*64 + mt*16 + grp;
#pragma unroll
        for (int nt = 0; nt < 4; nt++) {
            int nl = wn*32 + nt*8 + tid4*2;
            float gg0 = g_gate[b*R_ + nbase + nl], gg1 = g_gate[b*R_ + nbase + nl + 1];
            Es[m0l*LDE + nl]       = c[mt][nt][0]*gg0;
            Es[m0l*LDE + nl + 1]   = c[mt][nt][1]*gg1;
            Es[(m0l+8)*LDE + nl]   = c[mt][nt][2]*gg0;
            Es[(m0l+8)*LDE + nl+1] = c[mt][nt][3]*gg1;
        }
    }
    __syncthreads();

    int ch = t >> 7;
    int n  = t & 127;
    float ret = g_ret[b*R_ + nbase + n];
    size_t gb = ((size_t)(mbase + ch*64)) * R_ + nbase + n;
    float st = 0.f;
#pragma unroll 8
    for (int s = 0; s < CHUNK; s++) {
        st = fmaf(st, ret, Es[(ch*64 + s)*LDE + n]);
        g_sigh[gb + (size_t)s*R_] = __float2half_rn(st);
    }
    int chg = (mbase % S_) / CHUNK + ch;
    g_carry[(b*NCH + chg)*R_ + nbase + n] = st;
}

// ---- K4: apply chunk prefixes in-place on fp16 signal; final_state fp32 ----
__global__ __launch_bounds__(256) void k_scan2(const float* __restrict__ prev,
                                               float* __restrict__ fs_out,
                                               int write_fs) {
    int blk = blockIdx.x;
    int b = blk / NCH, ch = blk % NCH;
    int r = threadIdx.x;
    float ret = g_ret[b*R_ + r];
    float q = ret;
#pragma unroll
    for (int i = 0; i < 6; i++) q = q * q;   // ret^64
    float e = prev[b*R_ + r];
    for (int j = 0; j < ch; j++)
        e = fmaf(e, q, g_carry[(b*NCH + j)*R_ + r]);

    size_t base = ((size_t)(b*S_ + ch*CHUNK)) * R_ + r;
    float p = ret;
    float last = 0.f;
    for (int g = 0; g < CHUNK/8; g++) {
        float v[8];
#pragma unroll
        for (int j = 0; j < 8; j++) v[j] = __half2float(g_sigh[base + (size_t)(g*8+j)*R_]);
#pragma unroll
        for (int j = 0; j < 8; j++) {
            float o = fmaf(e, p, v[j]);
            g_sigh[base + (size_t)(g*8+j)*R_] = __float2half_rn(o);
            p *= ret;
            last = o;
        }
    }
    if (write_fs && ch == NCH-1)
        fs_out[b*R_ + r] = last;
}

// ---- K5: output GEMM (fp16) ----
__global__ __launch_bounds__(256, 2) void k5_output(float* __restrict__ out) {
    extern __shared__ float smem[];
    uint32_t sb = (uint32_t)__cvta_generic_to_shared(smem);

    int nbase = blockIdx.x * 128;
    int mbase = blockIdx.y * 128;
    int t = threadIdx.x;
    int warp = t >> 5, lane = t & 31;
    int wm = warp >> 2, wn = warp & 3;
    int grp = lane >> 2, tid4 = lane & 3;

    float c[4][4][4];
#pragma unroll
    for (int mt = 0; mt < 4; mt++)
#pragma unroll
        for (int nt = 0; nt < 4; nt++)
#pragma unroll
            for (int i = 0; i < 4; i++) c[mt][nt][i] = 0.f;

    const __half* Ag = g_sigh + (size_t)mbase * R_;
    const __half* Bg = g_outwh + (size_t)nbase * R_;

    auto prefetch = [&](int st, int kt) {
        uint32_t ao = sb + (uint32_t)(st * STAGE_B);
        uint32_t bo = sb + (uint32_t)((NST + st) * STAGE_B);
        int k0 = kt * 32;
#pragma unroll
        for (int i = 0; i < 2; i++) {
            int id = t + i*256;
            int row = id >> 2, seg = id & 3;
            cp16(ao + (uint32_t)((row*LH + seg*8) * 2), Ag + (size_t)row*R_ + k0 + seg*8);
            cp16(bo + (uint32_t)((row*LH + seg*8) * 2), Bg + (size_t)row*R_ + k0 + seg*8);
        }
        asm volatile("cp.async.commit_group;\n");
    };

    const int NK = R_ / 32;   // 8
    prefetch(0, 0); prefetch(1, 1); prefetch(2, 2);
    for (int kt = 0; kt < NK; kt++) {
        if (kt <= NK-3)      asm volatile("cp.async.wait_group 2;\n");
        else if (kt == NK-2) asm volatile("cp.async.wait_group 1;\n");
        else                 asm volatile("cp.async.wait_group 0;\n");
        __syncthreads();
        if (kt + 3 < NK) prefetch((kt+3) % NST, kt+3);
        int st = kt % NST;
        gemm16_stage(sb + (uint32_t)(st*STAGE_B), sb + (uint32_t)((NST+st)*STAGE_B),
                     wm, wn, lane, c);
    }

#pragma unroll
    for (int mt = 0; mt < 4; mt++) {
        int m0 = mbase + wm*64 + mt*16 + grp;
#pragma unroll
        for (int nt = 0; nt < 4; nt++) {
            int n = nbase + wn*32 + nt*8 + tid4*2;
            float2 v0 = make_float2(c[mt][nt][0], c[mt][nt][1]);
            float2 v1 = make_float2(c[mt][nt][2], c[mt][nt][3]);
            *(float2*)&out[(size_t)m0*D_ + n]     = v0;
            *(float2*)&out[(size_t)(m0+8)*D_ + n] = v1;
        }
    }
}

extern "C" void kernel_launch(void* const* d_in, const int* in_sizes, int n_in,
                              void* d_out, int out_size) {
    const float* x     = (const float*)d_in[0];
    const float* prev  = (const float*)d_in[1];
    const float* freq  = (const float*)d_in[2];
    const float* rbias = (const float*)d_in[3];
    const float* rw    = (const float*)d_in[4];
    const float* gw    = (const float*)d_in[5];
    const float* gbias = (const float*)d_in[6];
    const float* outw  = (const float*)d_in[7];
    float* out = (float*)d_out;

    const int SMEM_GEMM = 2*NST*STAGE_B;          // 81920
    const int SMEM_K3   = (SMEM_GEMM > 128*LDE*4) ? SMEM_GEMM : 128*LDE*4;
    cudaFuncSetAttribute(k3_resonance, cudaFuncAttributeMaxDynamicSharedMemorySize, SMEM_K3);
    cudaFuncSetAttribute(k5_output,    cudaFuncAttributeMaxDynamicSharedMemorySize, SMEM_GEMM);

    const int out_elems = B_*S_*D_;
    int write_fs = (out_size >= out_elems + B_*R_) ? 1 : 0;
    float* fs = out + out_elems;

    k0_zero<<<8, 1024>>>();
    k1_stats<<<256, 256>>>(x);
    k2_prep<<<256, 256>>>(freq, rbias, rw, gw, gbias);
    k2b_roundw<<<(D_*R_)/512, 256>>>(outw);
    k3_resonance<<<dim3(2, 256), 256, SMEM_K3>>>();
    k_scan2<<<B_*NCH, 256>>>(prev, fs, write_fs);
    k5_output<<<dim3(8, 256), 256, SMEM_GEMM>>>(out);
}